// round 15
// baseline (speedup 1.0000x reference)
#include <cuda_runtime.h>
#include <cuda_fp16.h>
#include <cstdint>

#define NUM_USERS 200000
#define NUM_ITEMS 100000
#define N_NODES   (NUM_USERS + NUM_ITEMS)     // users first, then items
#define EMB_DIM   64
#define D4        (EMB_DIM / 4)               // 16 float4 per fp32 row
#define HROW      16                          // 16 uint2 (8 B) per fp16 row (128 B)
#define MAX_EDGES 3000000
#define ADJ_CAP   (2 * MAX_EDGES + 8 * N_NODES)
#define NZROWS    1024                        // distributed zero rows
#define TAB_ROWS  (N_NODES + NZROWS)
#define CONV_T    (N_NODES * 8)               // conv threads (1 uint4 = 8 halves each)

#define SCAN_TPB    1024
#define SCAN_BLOCKS ((N_NODES + SCAN_TPB - 1) / SCAN_TPB)   // 293

// ---------------------------------------------------------------------------
// Scratch (__device__ globals; zero-initialized; no allocation anywhere).
// g_h0/g_h1: contiguous 128 B fp16 rows; rows N_NODES.. are permanent zeros.
// g_adj: 8-padded buckets, ids PRE-SCALED by HROW (uint2 units).
// ---------------------------------------------------------------------------
__device__ int      g_deg[N_NODES];           // self-cleaned by k_pull2
__device__ int      g_off[N_NODES];           // block-local exclusive PADDED offsets
__device__ int      g_bsum[SCAN_BLOCKS];
__device__ int      g_bbase[SCAN_BLOCKS];
__device__ int      g_ticket;
__device__ unsigned g_rank[MAX_EDGES];        // rank_s | rank_d<<16
__device__ int      g_adj[ADJ_CAP];
__device__ uint2    g_h0[(size_t)TAB_ROWS * HROW];   // x0 fp16 (+ zero rows)
__device__ uint2    g_h1[(size_t)TAB_ROWS * HROW];   // x1 fp16 (+ zero rows)

__device__ __forceinline__ int node_off(int node) {
    return g_off[node] + __ldg(&g_bbase[node >> 10]);
}
__device__ __forceinline__ int pad8(int d) { return (d + 7) & ~7; }

// ---------------------------------------------------------------------------
// 1. degree histogram; atomic return = rank (packed)
// ---------------------------------------------------------------------------
__global__ void k_count(const int* __restrict__ src, const int* __restrict__ dst,
                        int num_edges) {
    int t = blockIdx.x * blockDim.x + threadIdx.x;
    if (t >= num_edges) return;
    int s = __ldg(src + t), d = __ldg(dst + t);
    unsigned rs = (unsigned)atomicAdd(&g_deg[s], 1);
    unsigned rd = (unsigned)atomicAdd(&g_deg[NUM_USERS + d], 1);
    g_rank[t] = rs | (rd << 16);
}

// ---------------------------------------------------------------------------
// 2. convert x0 -> contiguous fp16 table (users then items)
// ---------------------------------------------------------------------------
__global__ void k_conv(const float4* __restrict__ u0, const float4* __restrict__ i0) {
    int c = blockIdx.x * blockDim.x + threadIdx.x;           // one uint4 (8 halves)
    if (c >= CONV_T) return;
    const int NU4 = NUM_USERS * D4;
    int f = c * 2;                                           // two float4 per uint4
    float4 a = (f < NU4)     ? __ldg(&u0[f])     : __ldg(&i0[f - NU4]);
    float4 b = (f + 1 < NU4) ? __ldg(&u0[f + 1]) : __ldg(&i0[f + 1 - NU4]);
    __half2 h0 = __floats2half2_rn(a.x, a.y), h1 = __floats2half2_rn(a.z, a.w);
    __half2 h2 = __floats2half2_rn(b.x, b.y), h3 = __floats2half2_rn(b.z, b.w);
    uint4 o;
    o.x = *reinterpret_cast<uint32_t*>(&h0);
    o.y = *reinterpret_cast<uint32_t*>(&h1);
    o.z = *reinterpret_cast<uint32_t*>(&h2);
    o.w = *reinterpret_cast<uint32_t*>(&h3);
    reinterpret_cast<uint4*>(g_h0)[c] = o;
}

// ---------------------------------------------------------------------------
// 3. scan PADDED degrees; last block scans block sums (ticket).
// ---------------------------------------------------------------------------
__global__ void k_scan1() {
    __shared__ int sh[SCAN_TPB];
    __shared__ int is_last;
    int tid = threadIdx.x;
    int gid = blockIdx.x * SCAN_TPB + tid;

    int v = (gid < N_NODES) ? pad8(g_deg[gid]) : 0;
    sh[tid] = v;
    __syncthreads();
    for (int ofs = 1; ofs < SCAN_TPB; ofs <<= 1) {
        int t = 0;
        if (tid >= ofs) t = sh[tid - ofs];
        __syncthreads();
        sh[tid] += t;
        __syncthreads();
    }
    int incl = sh[tid];
    if (gid < N_NODES) g_off[gid] = incl - v;
    if (tid == SCAN_TPB - 1) g_bsum[blockIdx.x] = incl;

    __threadfence();
    if (tid == 0) is_last = (atomicAdd(&g_ticket, 1) == gridDim.x - 1);
    __syncthreads();

    if (is_last) {
        __threadfence();
        int bv = 0;
        if (tid < 512) {
            bv = (tid < SCAN_BLOCKS) ? g_bsum[tid] : 0;
            sh[tid] = bv;
        }
        __syncthreads();
        for (int ofs = 1; ofs < 512; ofs <<= 1) {
            int t = 0;
            if (tid < 512 && tid >= ofs) t = sh[tid - ofs];
            __syncthreads();
            if (tid < 512) sh[tid] += t;
            __syncthreads();
        }
        if (tid < SCAN_BLOCKS) g_bbase[tid] = sh[tid] - bv;
        if (tid == 0) g_ticket = 0;
    }
}

// ---------------------------------------------------------------------------
// 4. bin + pad: PRE-SCALED ids; pads use DISTRIBUTED zero rows.  (capture slot)
// ---------------------------------------------------------------------------
__global__ void k_bin_pad(const int* __restrict__ src, const int* __restrict__ dst,
                          int num_edges) {
    int t = blockIdx.x * blockDim.x + threadIdx.x;
    if (t < num_edges) {
        int s = __ldg(src + t), d = __ldg(dst + t);
        int dn = NUM_USERS + d;
        unsigned r = g_rank[t];
        g_adj[node_off(s)  + (int)(r & 0xffffu)] = dn * HROW;
        g_adj[node_off(dn) + (int)(r >> 16)]     = s * HROW;
    } else {
        int node = t - num_edges;
        if (node < N_NODES) {
            int off = node_off(node);
            int deg = g_deg[node];
            int pd  = pad8(deg);
            int z   = (N_NODES + (node & (NZROWS - 1))) * HROW;   // distributed zero
            for (int k = deg; k < pd; k++) g_adj[off + k] = z;
        }
    }
}

// ---------------------------------------------------------------------------
// fp16 mean gather (R12-proven): group 0 owns neighbors 0-3 of each 8-chunk,
// group 1 owns 4-7. Indices: ONE int4 LDG.128 per group per chunk, pipelined.
// Lane owns 8 B of the contiguous 128 B row.
// ---------------------------------------------------------------------------
__device__ __forceinline__ float4 gather_mean_h(int off, int deg, int pdeg, int lane,
                                                const uint2* __restrict__ tab) {
    int grp = lane >> 4;
    int l4  = lane & 15;
    float ax = 0.f, ay = 0.f, az = 0.f, aw = 0.f;

    const int4* adj4 = reinterpret_cast<const int4*>(g_adj);
    int i4 = (off >> 2) + grp;                               // off is 8-aligned
    int4 n = __ldg(&adj4[i4]);                               // prefetch chunk 0

    for (int k = 0; k < pdeg; k += 8) {
        uint2 v0 = __ldg(&tab[n.x + l4]);                    // pre-scaled ids
        uint2 v1 = __ldg(&tab[n.y + l4]);
        uint2 v2 = __ldg(&tab[n.z + l4]);
        uint2 v3 = __ldg(&tab[n.w + l4]);

        i4 += 2;                                             // prefetch chunk k+1
        if (k + 8 < pdeg) n = __ldg(&adj4[i4]);

        __half2 s01lo = __hadd2(*reinterpret_cast<__half2*>(&v0.x),
                                *reinterpret_cast<__half2*>(&v1.x));
        __half2 s01hi = __hadd2(*reinterpret_cast<__half2*>(&v0.y),
                                *reinterpret_cast<__half2*>(&v1.y));
        __half2 s23lo = __hadd2(*reinterpret_cast<__half2*>(&v2.x),
                                *reinterpret_cast<__half2*>(&v3.x));
        __half2 s23hi = __hadd2(*reinterpret_cast<__half2*>(&v2.y),
                                *reinterpret_cast<__half2*>(&v3.y));
        __half2 slo = __hadd2(s01lo, s23lo);
        __half2 shi = __hadd2(s01hi, s23hi);

        float2 flo = __half22float2(slo);
        float2 fhi = __half22float2(shi);
        ax += flo.x; ay += flo.y; az += fhi.x; aw += fhi.y;
    }

    ax += __shfl_xor_sync(0xffffffffu, ax, 16);
    ay += __shfl_xor_sync(0xffffffffu, ay, 16);
    az += __shfl_xor_sync(0xffffffffu, az, 16);
    aw += __shfl_xor_sync(0xffffffffu, aw, 16);

    float inv = deg > 0 ? 1.f / (float)deg : 0.f;
    return make_float4(ax * inv, ay * inv, az * inv, aw * inv);
}

// ---------------------------------------------------------------------------
// 5. layer-1 pull: x1 = mean(x0 over neighbors), stored fp16
// ---------------------------------------------------------------------------
__global__ void __launch_bounds__(256, 7)
k_pull1() {
    int warp = (blockIdx.x * blockDim.x + threadIdx.x) >> 5;
    int lane = threadIdx.x & 31;
    if (warp >= N_NODES) return;

    int off  = node_off(warp);
    int deg  = g_deg[warp];
    int pdeg = pad8(deg);
    float4 m = gather_mean_h(off, deg, pdeg, lane, g_h0);

    if (lane < 16) {
        __half2 lo = __floats2half2_rn(m.x, m.y);
        __half2 hi = __floats2half2_rn(m.z, m.w);
        g_h1[warp * HROW + lane] = make_uint2(*reinterpret_cast<uint32_t*>(&lo),
                                              *reinterpret_cast<uint32_t*>(&hi));
    }
}

// ---------------------------------------------------------------------------
// 6. layer-2 pull fused with final combine; x0/x1 read fp16 (L2-resident).
//    out[n] = (x0 + x1 + mean_neighbors(x1)) / 3 ; self-cleans g_deg.
// ---------------------------------------------------------------------------
__global__ void __launch_bounds__(256, 7)
k_pull2(float4* __restrict__ out) {
    int warp = (blockIdx.x * blockDim.x + threadIdx.x) >> 5;
    int lane = threadIdx.x & 31;
    if (warp >= N_NODES) return;

    int off  = node_off(warp);
    int deg  = g_deg[warp];
    int pdeg = pad8(deg);
    float4 m = gather_mean_h(off, deg, pdeg, lane, g_h1);    // x2

    if (lane < 16) {
        int ri = warp * HROW + lane;
        uint2 av = __ldg(&g_h0[ri]);                         // x0 fp16
        uint2 bv = g_h1[ri];                                 // x1 fp16
        float2 alo = __half22float2(*reinterpret_cast<__half2*>(&av.x));
        float2 ahi = __half22float2(*reinterpret_cast<__half2*>(&av.y));
        float2 blo = __half22float2(*reinterpret_cast<__half2*>(&bv.x));
        float2 bhi = __half22float2(*reinterpret_cast<__half2*>(&bv.y));
        const float third = 1.0f / 3.0f;
        out[warp * D4 + lane] = make_float4((alo.x + blo.x + m.x) * third,
                                            (alo.y + blo.y + m.y) * third,
                                            (ahi.x + bhi.x + m.z) * third,
                                            (ahi.y + bhi.y + m.w) * third);
    }
    if (lane == 0) g_deg[warp] = 0;                          // self-clean
}

// ---------------------------------------------------------------------------
// kernel_launch: 6 launches; k_bin_pad is launch #4 -> ncu capture slot.
// ---------------------------------------------------------------------------
extern "C" void kernel_launch(void* const* d_in, const int* in_sizes, int n_in,
                              void* d_out, int out_size) {
    const float4* user_emb = (const float4*)d_in[0];
    const float4* item_emb = (const float4*)d_in[1];
    const int*    src      = (const int*)d_in[2];
    const int*    dst      = (const int*)d_in[3];
    const int     E        = in_sizes[2];
    float4*       out      = (float4*)d_out;

    const int TPB = 256;
    const int edge_blocks = (E + TPB - 1) / TPB;
    const int conv_blocks = (CONV_T + TPB - 1) / TPB;
    const int bp_blocks   = (E + N_NODES + TPB - 1) / TPB;
    const long pull_threads = (long)N_NODES * 32;
    const int  pull_blocks  = (int)((pull_threads + TPB - 1) / TPB);

    k_count<<<edge_blocks, TPB>>>(src, dst, E);
    k_conv<<<conv_blocks, TPB>>>(user_emb, item_emb);
    k_scan1<<<SCAN_BLOCKS, SCAN_TPB>>>();
    k_bin_pad<<<bp_blocks, TPB>>>(src, dst, E);              // capture slot
    k_pull1<<<pull_blocks, TPB>>>();
    k_pull2<<<pull_blocks, TPB>>>(out);
}

// round 16
// speedup vs baseline: 1.0368x; 1.0368x over previous
#include <cuda_runtime.h>
#include <cuda_fp16.h>
#include <cstdint>

#define NUM_USERS 200000
#define NUM_ITEMS 100000
#define N_NODES   (NUM_USERS + NUM_ITEMS)     // users first, then items
#define EMB_DIM   64
#define D4        (EMB_DIM / 4)               // 16 float4 per fp32 row
#define HROW      16                          // 16 uint2 (8 B) per fp16 row (128 B)
#define MAX_EDGES 3000000
#define ADJ_CAP   (2 * MAX_EDGES + 8 * N_NODES)
#define NZROWS    1024                        // distributed zero rows
#define TAB_ROWS  (N_NODES + NZROWS)
#define CONV_T    (N_NODES * 8)               // conv threads (1 uint4 = 8 halves each)

#define SCAN_TPB    1024
#define SCAN_BLOCKS ((N_NODES + SCAN_TPB - 1) / SCAN_TPB)   // 293

// ---------------------------------------------------------------------------
// Scratch (__device__ globals; zero-initialized; no allocation anywhere).
// g_h0/g_h1: contiguous 128 B fp16 rows; rows N_NODES.. are permanent zeros.
// g_adj: 8-padded buckets, ids PRE-SCALED by HROW (uint2 units).
// g_cursor: block-local bucket cursors (atomic slot allocation in bin).
// ---------------------------------------------------------------------------
__device__ int      g_deg[N_NODES];           // self-cleaned by k_pull2
__device__ int      g_off[N_NODES];           // block-local exclusive PADDED offsets
__device__ int      g_cursor[N_NODES];        // copy of g_off, consumed by bin
__device__ int      g_bsum[SCAN_BLOCKS];
__device__ int      g_bbase[SCAN_BLOCKS];
__device__ int      g_ticket;
__device__ int      g_adj[ADJ_CAP];
__device__ uint2    g_h0[(size_t)TAB_ROWS * HROW];   // x0 fp16 (+ zero rows)
__device__ uint2    g_h1[(size_t)TAB_ROWS * HROW];   // x1 fp16 (+ zero rows)

__device__ __forceinline__ int node_off(int node) {
    return g_off[node] + __ldg(&g_bbase[node >> 10]);
}
__device__ __forceinline__ int pad8(int d) { return (d + 7) & ~7; }

// ---------------------------------------------------------------------------
// 1. count + convert fused: edge threads do pure RED.ADD degree histogram
//    (no return -> no rank array); extra threads convert x0 -> fp16 table.
// ---------------------------------------------------------------------------
__global__ void k_count_conv(const int* __restrict__ src, const int* __restrict__ dst,
                             const float4* __restrict__ u0, const float4* __restrict__ i0,
                             int num_edges) {
    int t = blockIdx.x * blockDim.x + threadIdx.x;
    if (t < num_edges) {
        atomicAdd(&g_deg[__ldg(src + t)], 1);                // RED (no return)
        atomicAdd(&g_deg[NUM_USERS + __ldg(dst + t)], 1);
    } else {
        int c = t - num_edges;                               // one uint4 (8 halves)
        if (c < CONV_T) {
            const int NU4 = NUM_USERS * D4;
            int f = c * 2;                                   // two float4 per uint4
            float4 a = (f < NU4)     ? __ldg(&u0[f])     : __ldg(&i0[f - NU4]);
            float4 b = (f + 1 < NU4) ? __ldg(&u0[f + 1]) : __ldg(&i0[f + 1 - NU4]);
            __half2 h0 = __floats2half2_rn(a.x, a.y), h1 = __floats2half2_rn(a.z, a.w);
            __half2 h2 = __floats2half2_rn(b.x, b.y), h3 = __floats2half2_rn(b.z, b.w);
            uint4 o;
            o.x = *reinterpret_cast<uint32_t*>(&h0);
            o.y = *reinterpret_cast<uint32_t*>(&h1);
            o.z = *reinterpret_cast<uint32_t*>(&h2);
            o.w = *reinterpret_cast<uint32_t*>(&h3);
            reinterpret_cast<uint4*>(g_h0)[c] = o;
        }
    }
}

// ---------------------------------------------------------------------------
// 2. scan PADDED degrees -> g_off AND g_cursor; last block scans block sums.
// ---------------------------------------------------------------------------
__global__ void k_scan1() {
    __shared__ int sh[SCAN_TPB];
    __shared__ int is_last;
    int tid = threadIdx.x;
    int gid = blockIdx.x * SCAN_TPB + tid;

    int v = (gid < N_NODES) ? pad8(g_deg[gid]) : 0;
    sh[tid] = v;
    __syncthreads();
    for (int ofs = 1; ofs < SCAN_TPB; ofs <<= 1) {
        int t = 0;
        if (tid >= ofs) t = sh[tid - ofs];
        __syncthreads();
        sh[tid] += t;
        __syncthreads();
    }
    int incl = sh[tid];
    if (gid < N_NODES) {
        int ex = incl - v;                                   // block-local exclusive
        g_off[gid]    = ex;
        g_cursor[gid] = ex;                                  // bin's atomic cursor
    }
    if (tid == SCAN_TPB - 1) g_bsum[blockIdx.x] = incl;

    __threadfence();
    if (tid == 0) is_last = (atomicAdd(&g_ticket, 1) == gridDim.x - 1);
    __syncthreads();

    if (is_last) {
        __threadfence();
        int bv = 0;
        if (tid < 512) {
            bv = (tid < SCAN_BLOCKS) ? g_bsum[tid] : 0;
            sh[tid] = bv;
        }
        __syncthreads();
        for (int ofs = 1; ofs < 512; ofs <<= 1) {
            int t = 0;
            if (tid < 512 && tid >= ofs) t = sh[tid - ofs];
            __syncthreads();
            if (tid < 512) sh[tid] += t;
            __syncthreads();
        }
        if (tid < SCAN_BLOCKS) g_bbase[tid] = sh[tid] - bv;  // exclusive base
        if (tid == 0) g_ticket = 0;                          // reset for next replay
    }
}

// ---------------------------------------------------------------------------
// 3. bin + pad: slots from atomic cursors (no g_off loads, no rank array);
//    PRE-SCALED ids; pads use DISTRIBUTED zero rows.
// ---------------------------------------------------------------------------
__global__ void k_bin_pad(const int* __restrict__ src, const int* __restrict__ dst,
                          int num_edges) {
    int t = blockIdx.x * blockDim.x + threadIdx.x;
    if (t < num_edges) {
        int s = __ldg(src + t), d = __ldg(dst + t);
        int dn = NUM_USERS + d;
        int sl0 = atomicAdd(&g_cursor[s], 1)  + __ldg(&g_bbase[s >> 10]);
        int sl1 = atomicAdd(&g_cursor[dn], 1) + __ldg(&g_bbase[dn >> 10]);
        g_adj[sl0] = dn * HROW;
        g_adj[sl1] = s * HROW;
    } else {
        int node = t - num_edges;
        if (node < N_NODES) {
            int off = node_off(node);
            int deg = g_deg[node];
            int pd  = pad8(deg);
            int z   = (N_NODES + (node & (NZROWS - 1))) * HROW;   // distributed zero
            for (int k = deg; k < pd; k++) g_adj[off + k] = z;
        }
    }
}

// ---------------------------------------------------------------------------
// fp16 mean gather (R12-proven): group 0 owns neighbors 0-3 of each 8-chunk,
// group 1 owns 4-7. Indices: ONE int4 LDG.128 per group per chunk, pipelined.
// Lane owns 8 B of the contiguous 128 B row.
// ---------------------------------------------------------------------------
__device__ __forceinline__ float4 gather_mean_h(int off, int deg, int pdeg, int lane,
                                                const uint2* __restrict__ tab) {
    int grp = lane >> 4;
    int l4  = lane & 15;
    float ax = 0.f, ay = 0.f, az = 0.f, aw = 0.f;

    const int4* adj4 = reinterpret_cast<const int4*>(g_adj);
    int i4 = (off >> 2) + grp;                               // off is 8-aligned
    int4 n = __ldg(&adj4[i4]);                               // prefetch chunk 0

    for (int k = 0; k < pdeg; k += 8) {
        uint2 v0 = __ldg(&tab[n.x + l4]);                    // pre-scaled ids
        uint2 v1 = __ldg(&tab[n.y + l4]);
        uint2 v2 = __ldg(&tab[n.z + l4]);
        uint2 v3 = __ldg(&tab[n.w + l4]);

        i4 += 2;                                             // prefetch chunk k+1
        if (k + 8 < pdeg) n = __ldg(&adj4[i4]);

        __half2 s01lo = __hadd2(*reinterpret_cast<__half2*>(&v0.x),
                                *reinterpret_cast<__half2*>(&v1.x));
        __half2 s01hi = __hadd2(*reinterpret_cast<__half2*>(&v0.y),
                                *reinterpret_cast<__half2*>(&v1.y));
        __half2 s23lo = __hadd2(*reinterpret_cast<__half2*>(&v2.x),
                                *reinterpret_cast<__half2*>(&v3.x));
        __half2 s23hi = __hadd2(*reinterpret_cast<__half2*>(&v2.y),
                                *reinterpret_cast<__half2*>(&v3.y));
        __half2 slo = __hadd2(s01lo, s23lo);
        __half2 shi = __hadd2(s01hi, s23hi);

        float2 flo = __half22float2(slo);
        float2 fhi = __half22float2(shi);
        ax += flo.x; ay += flo.y; az += fhi.x; aw += fhi.y;
    }

    ax += __shfl_xor_sync(0xffffffffu, ax, 16);
    ay += __shfl_xor_sync(0xffffffffu, ay, 16);
    az += __shfl_xor_sync(0xffffffffu, az, 16);
    aw += __shfl_xor_sync(0xffffffffu, aw, 16);

    float inv = deg > 0 ? 1.f / (float)deg : 0.f;
    return make_float4(ax * inv, ay * inv, az * inv, aw * inv);
}

// ---------------------------------------------------------------------------
// 4. layer-1 pull: x1 = mean(x0 over neighbors), stored fp16  (capture slot)
// ---------------------------------------------------------------------------
__global__ void __launch_bounds__(256, 7)
k_pull1() {
    int warp = (blockIdx.x * blockDim.x + threadIdx.x) >> 5;
    int lane = threadIdx.x & 31;
    if (warp >= N_NODES) return;

    int off  = node_off(warp);
    int deg  = g_deg[warp];
    int pdeg = pad8(deg);
    float4 m = gather_mean_h(off, deg, pdeg, lane, g_h0);

    if (lane < 16) {
        __half2 lo = __floats2half2_rn(m.x, m.y);
        __half2 hi = __floats2half2_rn(m.z, m.w);
        g_h1[warp * HROW + lane] = make_uint2(*reinterpret_cast<uint32_t*>(&lo),
                                              *reinterpret_cast<uint32_t*>(&hi));
    }
}

// ---------------------------------------------------------------------------
// 5. layer-2 pull fused with final combine; x0/x1 read fp16 (L2-resident).
//    out[n] = (x0 + x1 + mean_neighbors(x1)) / 3 ; self-cleans g_deg.
// ---------------------------------------------------------------------------
__global__ void __launch_bounds__(256, 7)
k_pull2(float4* __restrict__ out) {
    int warp = (blockIdx.x * blockDim.x + threadIdx.x) >> 5;
    int lane = threadIdx.x & 31;
    if (warp >= N_NODES) return;

    int off  = node_off(warp);
    int deg  = g_deg[warp];
    int pdeg = pad8(deg);
    float4 m = gather_mean_h(off, deg, pdeg, lane, g_h1);    // x2

    if (lane < 16) {
        int ri = warp * HROW + lane;
        uint2 av = __ldg(&g_h0[ri]);                         // x0 fp16
        uint2 bv = g_h1[ri];                                 // x1 fp16
        float2 alo = __half22float2(*reinterpret_cast<__half2*>(&av.x));
        float2 ahi = __half22float2(*reinterpret_cast<__half2*>(&av.y));
        float2 blo = __half22float2(*reinterpret_cast<__half2*>(&bv.x));
        float2 bhi = __half22float2(*reinterpret_cast<__half2*>(&bv.y));
        const float third = 1.0f / 3.0f;
        out[warp * D4 + lane] = make_float4((alo.x + blo.x + m.x) * third,
                                            (alo.y + blo.y + m.y) * third,
                                            (ahi.x + bhi.x + m.z) * third,
                                            (ahi.y + bhi.y + m.w) * third);
    }
    if (lane == 0) g_deg[warp] = 0;                          // self-clean
}

// ---------------------------------------------------------------------------
// kernel_launch: 5 launches; k_pull1 is launch #4 -> ncu capture slot.
// ---------------------------------------------------------------------------
extern "C" void kernel_launch(void* const* d_in, const int* in_sizes, int n_in,
                              void* d_out, int out_size) {
    const float4* user_emb = (const float4*)d_in[0];
    const float4* item_emb = (const float4*)d_in[1];
    const int*    src      = (const int*)d_in[2];
    const int*    dst      = (const int*)d_in[3];
    const int     E        = in_sizes[2];
    float4*       out      = (float4*)d_out;

    const int TPB = 256;
    const int cc_blocks = (E + CONV_T + TPB - 1) / TPB;
    const int bp_blocks = (E + N_NODES + TPB - 1) / TPB;
    const long pull_threads = (long)N_NODES * 32;
    const int  pull_blocks  = (int)((pull_threads + TPB - 1) / TPB);

    k_count_conv<<<cc_blocks, TPB>>>(src, dst, user_emb, item_emb, E);
    k_scan1<<<SCAN_BLOCKS, SCAN_TPB>>>();
    k_bin_pad<<<bp_blocks, TPB>>>(src, dst, E);
    k_pull1<<<pull_blocks, TPB>>>();
    k_pull2<<<pull_blocks, TPB>>>(out);
}

// round 17
// speedup vs baseline: 1.1698x; 1.1283x over previous
#include <cuda_runtime.h>
#include <cuda_fp16.h>
#include <cstdint>

#define NUM_USERS 200000
#define NUM_ITEMS 100000
#define N_NODES   (NUM_USERS + NUM_ITEMS)     // users first, then items
#define EMB_DIM   64
#define D4        (EMB_DIM / 4)               // 16 float4 per fp32 row
#define HROW      16                          // 16 uint2 (8 B) per fp16 row (128 B)
#define MAX_EDGES 3000000
#define ADJ_CAP   (2 * MAX_EDGES + 8 * N_NODES + 4)   // +4 slack for prefetch
#define NZROWS    1024                        // distributed zero rows
#define TAB_ROWS  (N_NODES + NZROWS)
#define CONV_T    (N_NODES * 8)               // conv threads (1 uint4 = 8 halves each)

#define SCAN_TPB    1024
#define SCAN_BLOCKS ((N_NODES + SCAN_TPB - 1) / SCAN_TPB)   // 293

// ---------------------------------------------------------------------------
// Scratch (__device__ globals; zero-initialized; no allocation anywhere).
// g_h0/g_h1: contiguous 128 B fp16 rows; rows N_NODES.. are permanent zeros.
// g_adj: 4-padded buckets, ids PRE-SCALED by HROW (uint2 units).
// ---------------------------------------------------------------------------
__device__ int      g_deg[N_NODES];           // self-cleaned by k_pull2
__device__ int      g_off[N_NODES];           // block-local exclusive PADDED offsets
__device__ int      g_cursor[N_NODES];        // copy of g_off, consumed by bin
__device__ int      g_bsum[SCAN_BLOCKS];
__device__ int      g_bbase[SCAN_BLOCKS];
__device__ int      g_ticket;
__device__ int      g_adj[ADJ_CAP];
__device__ uint2    g_h0[(size_t)TAB_ROWS * HROW];   // x0 fp16 (+ zero rows)
__device__ uint2    g_h1[(size_t)TAB_ROWS * HROW];   // x1 fp16 (+ zero rows)

__device__ __forceinline__ int node_off(int node) {
    return g_off[node] + __ldg(&g_bbase[node >> 10]);
}
__device__ __forceinline__ int pad4(int d) { return (d + 3) & ~3; }

// ---------------------------------------------------------------------------
// 1. count + convert fused: edge threads do pure RED.ADD degree histogram;
//    extra threads convert x0 -> fp16 table.
// ---------------------------------------------------------------------------
__global__ void k_count_conv(const int* __restrict__ src, const int* __restrict__ dst,
                             const float4* __restrict__ u0, const float4* __restrict__ i0,
                             int num_edges) {
    int t = blockIdx.x * blockDim.x + threadIdx.x;
    if (t < num_edges) {
        atomicAdd(&g_deg[__ldg(src + t)], 1);                // RED (no return)
        atomicAdd(&g_deg[NUM_USERS + __ldg(dst + t)], 1);
    } else {
        int c = t - num_edges;                               // one uint4 (8 halves)
        if (c < CONV_T) {
            const int NU4 = NUM_USERS * D4;
            int f = c * 2;                                   // two float4 per uint4
            float4 a = (f < NU4)     ? __ldg(&u0[f])     : __ldg(&i0[f - NU4]);
            float4 b = (f + 1 < NU4) ? __ldg(&u0[f + 1]) : __ldg(&i0[f + 1 - NU4]);
            __half2 h0 = __floats2half2_rn(a.x, a.y), h1 = __floats2half2_rn(a.z, a.w);
            __half2 h2 = __floats2half2_rn(b.x, b.y), h3 = __floats2half2_rn(b.z, b.w);
            uint4 o;
            o.x = *reinterpret_cast<uint32_t*>(&h0);
            o.y = *reinterpret_cast<uint32_t*>(&h1);
            o.z = *reinterpret_cast<uint32_t*>(&h2);
            o.w = *reinterpret_cast<uint32_t*>(&h3);
            reinterpret_cast<uint4*>(g_h0)[c] = o;
        }
    }
}

// ---------------------------------------------------------------------------
// 2. scan PADDED (x4) degrees -> g_off AND g_cursor; last block scans sums.
// ---------------------------------------------------------------------------
__global__ void k_scan1() {
    __shared__ int sh[SCAN_TPB];
    __shared__ int is_last;
    int tid = threadIdx.x;
    int gid = blockIdx.x * SCAN_TPB + tid;

    int v = (gid < N_NODES) ? pad4(g_deg[gid]) : 0;
    sh[tid] = v;
    __syncthreads();
    for (int ofs = 1; ofs < SCAN_TPB; ofs <<= 1) {
        int t = 0;
        if (tid >= ofs) t = sh[tid - ofs];
        __syncthreads();
        sh[tid] += t;
        __syncthreads();
    }
    int incl = sh[tid];
    if (gid < N_NODES) {
        int ex = incl - v;
        g_off[gid]    = ex;
        g_cursor[gid] = ex;
    }
    if (tid == SCAN_TPB - 1) g_bsum[blockIdx.x] = incl;

    __threadfence();
    if (tid == 0) is_last = (atomicAdd(&g_ticket, 1) == gridDim.x - 1);
    __syncthreads();

    if (is_last) {
        __threadfence();
        int bv = 0;
        if (tid < 512) {
            bv = (tid < SCAN_BLOCKS) ? g_bsum[tid] : 0;
            sh[tid] = bv;
        }
        __syncthreads();
        for (int ofs = 1; ofs < 512; ofs <<= 1) {
            int t = 0;
            if (tid < 512 && tid >= ofs) t = sh[tid - ofs];
            __syncthreads();
            if (tid < 512) sh[tid] += t;
            __syncthreads();
        }
        if (tid < SCAN_BLOCKS) g_bbase[tid] = sh[tid] - bv;
        if (tid == 0) g_ticket = 0;
    }
}

// ---------------------------------------------------------------------------
// 3. bin + pad: slots from atomic cursors; PRE-SCALED ids; distributed zeros.
// ---------------------------------------------------------------------------
__global__ void k_bin_pad(const int* __restrict__ src, const int* __restrict__ dst,
                          int num_edges) {
    int t = blockIdx.x * blockDim.x + threadIdx.x;
    if (t < num_edges) {
        int s = __ldg(src + t), d = __ldg(dst + t);
        int dn = NUM_USERS + d;
        int sl0 = atomicAdd(&g_cursor[s], 1)  + __ldg(&g_bbase[s >> 10]);
        int sl1 = atomicAdd(&g_cursor[dn], 1) + __ldg(&g_bbase[dn >> 10]);
        g_adj[sl0] = dn * HROW;
        g_adj[sl1] = s * HROW;
    } else {
        int node = t - num_edges;
        if (node < N_NODES) {
            int off = node_off(node);
            int deg = g_deg[node];
            int pd  = pad4(deg);
            int z   = (N_NODES + (node & (NZROWS - 1))) * HROW;   // distributed zero
            for (int k = deg; k < pd; k++) g_adj[off + k] = z;
        }
    }
}

// ---------------------------------------------------------------------------
// fp16 mean gather per 16-LANE GROUP (one node per group, 2 per warp).
// Chunk = 4 neighbors: indices via ONE int4 LDG.128, pipelined one ahead.
// Lane owns 8 B of the contiguous 128 B row. No cross-group combine needed.
// ---------------------------------------------------------------------------
__device__ __forceinline__ float4 gather_mean_h16(int off, int deg, int pdeg, int l4,
                                                  const uint2* __restrict__ tab) {
    float ax = 0.f, ay = 0.f, az = 0.f, aw = 0.f;

    const int4* adj4 = reinterpret_cast<const int4*>(g_adj);
    int i4 = off >> 2;                                       // off is 4-aligned
    int4 n = __ldg(&adj4[i4]);                               // prefetch chunk 0

    for (int k = 0; k < pdeg; k += 4) {
        uint2 v0 = __ldg(&tab[n.x + l4]);                    // pre-scaled ids
        uint2 v1 = __ldg(&tab[n.y + l4]);
        uint2 v2 = __ldg(&tab[n.z + l4]);
        uint2 v3 = __ldg(&tab[n.w + l4]);

        i4 += 1;                                             // prefetch chunk k+1
        if (k + 4 < pdeg) n = __ldg(&adj4[i4]);

        __half2 s01lo = __hadd2(*reinterpret_cast<__half2*>(&v0.x),
                                *reinterpret_cast<__half2*>(&v1.x));
        __half2 s01hi = __hadd2(*reinterpret_cast<__half2*>(&v0.y),
                                *reinterpret_cast<__half2*>(&v1.y));
        __half2 s23lo = __hadd2(*reinterpret_cast<__half2*>(&v2.x),
                                *reinterpret_cast<__half2*>(&v3.x));
        __half2 s23hi = __hadd2(*reinterpret_cast<__half2*>(&v2.y),
                                *reinterpret_cast<__half2*>(&v3.y));
        __half2 slo = __hadd2(s01lo, s23lo);
        __half2 shi = __hadd2(s01hi, s23hi);

        float2 flo = __half22float2(slo);
        float2 fhi = __half22float2(shi);
        ax += flo.x; ay += flo.y; az += fhi.x; aw += fhi.y;
    }

    float inv = deg > 0 ? 1.f / (float)deg : 0.f;
    return make_float4(ax * inv, ay * inv, az * inv, aw * inv);
}

// ---------------------------------------------------------------------------
// 4. layer-1 pull: 2 nodes per warp; x1 stored fp16  (capture slot)
// ---------------------------------------------------------------------------
__global__ void __launch_bounds__(256, 7)
k_pull1() {
    int t    = blockIdx.x * blockDim.x + threadIdx.x;
    int node = (t >> 5) * 2 + ((t >> 4) & 1);                // 2 nodes per warp
    int l4   = t & 15;
    if (node >= N_NODES) return;

    int off  = node_off(node);
    int deg  = g_deg[node];
    int pdeg = pad4(deg);
    float4 m = gather_mean_h16(off, deg, pdeg, l4, g_h0);

    __half2 lo = __floats2half2_rn(m.x, m.y);
    __half2 hi = __floats2half2_rn(m.z, m.w);
    g_h1[node * HROW + l4] = make_uint2(*reinterpret_cast<uint32_t*>(&lo),
                                        *reinterpret_cast<uint32_t*>(&hi));
}

// ---------------------------------------------------------------------------
// 5. layer-2 pull fused with final combine; out written STREAMING (__stwt) so
//    the 77 MB write-once output doesn't evict the gather tables from L2.
// ---------------------------------------------------------------------------
__global__ void __launch_bounds__(256, 7)
k_pull2(float4* __restrict__ out) {
    int t    = blockIdx.x * blockDim.x + threadIdx.x;
    int node = (t >> 5) * 2 + ((t >> 4) & 1);
    int l4   = t & 15;
    if (node >= N_NODES) return;

    int off  = node_off(node);
    int deg  = g_deg[node];
    int pdeg = pad4(deg);
    float4 m = gather_mean_h16(off, deg, pdeg, l4, g_h1);    // x2

    int ri = node * HROW + l4;
    uint2 av = __ldg(&g_h0[ri]);                             // x0 fp16
    uint2 bv = g_h1[ri];                                     // x1 fp16
    float2 alo = __half22float2(*reinterpret_cast<__half2*>(&av.x));
    float2 ahi = __half22float2(*reinterpret_cast<__half2*>(&av.y));
    float2 blo = __half22float2(*reinterpret_cast<__half2*>(&bv.x));
    float2 bhi = __half22float2(*reinterpret_cast<__half2*>(&bv.y));
    const float third = 1.0f / 3.0f;
    float4 o = make_float4((alo.x + blo.x + m.x) * third,
                           (alo.y + blo.y + m.y) * third,
                           (ahi.x + bhi.x + m.z) * third,
                           (ahi.y + bhi.y + m.w) * third);
    __stwt(&out[node * D4 + l4], o);                         // streaming store

    if (l4 == 0) g_deg[node] = 0;                            // self-clean (per group)
}

// ---------------------------------------------------------------------------
// kernel_launch: 5 launches; k_pull1 is launch #4 -> ncu capture slot.
// ---------------------------------------------------------------------------
extern "C" void kernel_launch(void* const* d_in, const int* in_sizes, int n_in,
                              void* d_out, int out_size) {
    const float4* user_emb = (const float4*)d_in[0];
    const float4* item_emb = (const float4*)d_in[1];
    const int*    src      = (const int*)d_in[2];
    const int*    dst      = (const int*)d_in[3];
    const int     E        = in_sizes[2];
    float4*       out      = (float4*)d_out;

    const int TPB = 256;
    const int cc_blocks = (E + CONV_T + TPB - 1) / TPB;
    const int bp_blocks = (E + N_NODES + TPB - 1) / TPB;
    const long pull_threads = (long)((N_NODES + 1) / 2) * 32;   // 2 nodes per warp
    const int  pull_blocks  = (int)((pull_threads + TPB - 1) / TPB);

    k_count_conv<<<cc_blocks, TPB>>>(src, dst, user_emb, item_emb, E);
    k_scan1<<<SCAN_BLOCKS, SCAN_TPB>>>();
    k_bin_pad<<<bp_blocks, TPB>>>(src, dst, E);
    k_pull1<<<pull_blocks, TPB>>>();
    k_pull2<<<pull_blocks, TPB>>>(out);
}